// round 1
// baseline (speedup 1.0000x reference)
#include <cuda_runtime.h>
#include <cuda_bf16.h>
#include <math.h>
#include <stdint.h>

// ---------------------------------------------------------------------------
// Problem constants
// ---------------------------------------------------------------------------
#define B_    2
#define S_    2048
#define D_    768
#define H_    12
#define DH_   64
#define F_    2048
#define ROWS_ (B_ * S_)          // 4096
#define KKEEP 1228               // int(2048*0.6)
#define KTH_IDX (S_ - KKEEP)     // 820 (ascending sort index of k-th largest)

// ---------------------------------------------------------------------------
// Scratch (static device allocations — no cudaMalloc allowed)
// ---------------------------------------------------------------------------
__device__ float g_normed[ROWS_ * D_];
__device__ float g_q[ROWS_ * D_];
__device__ float g_k[ROWS_ * D_];
__device__ float g_v[ROWS_ * D_];
__device__ float g_ctx[ROWS_ * D_];
__device__ float g_h2[ROWS_ * D_];
__device__ float g_n2[ROWS_ * D_];
__device__ float g_gated[ROWS_ * D_];
__device__ float g_h1[ROWS_ * F_];
__device__ float g_u[ROWS_ * F_];
__device__ float g_scores[ROWS_];
__device__ float g_active[ROWS_];
__device__ float g_rowmask[ROWS_];
__device__ float g_kth[B_];

// ---------------------------------------------------------------------------
// Helpers
// ---------------------------------------------------------------------------
__device__ __forceinline__ float sigmoidf_(float x) {
    return 1.0f / (1.0f + __expf(-x));
}

__device__ float blockReduceSum(float v) {
    __shared__ float sh[32];
    int lane = threadIdx.x & 31;
    int wid  = threadIdx.x >> 5;
    #pragma unroll
    for (int o = 16; o; o >>= 1) v += __shfl_down_sync(0xFFFFFFFFu, v, o);
    if (lane == 0) sh[wid] = v;
    __syncthreads();
    int nw = blockDim.x >> 5;
    v = (threadIdx.x < nw) ? sh[threadIdx.x] : 0.0f;
    if (wid == 0) {
        #pragma unroll
        for (int o = 16; o; o >>= 1) v += __shfl_down_sync(0xFFFFFFFFu, v, o);
        if (lane == 0) sh[0] = v;
    }
    __syncthreads();
    float r = sh[0];
    __syncthreads();
    return r;
}

// ---------------------------------------------------------------------------
// K1: fused depth router + rmsnorm(g1) + token score
// one block per row (4096 blocks, 256 threads)
// ---------------------------------------------------------------------------
__global__ void pre_kernel(const float* __restrict__ hidden,
                           const float* __restrict__ g1,
                           const float* __restrict__ w_mod,
                           const float* __restrict__ b_mod,
                           const float* __restrict__ w_tok,
                           const float* __restrict__ b_tok,
                           float* __restrict__ normed,
                           float* __restrict__ scores,
                           float* __restrict__ active,
                           float* __restrict__ probs_out) {
    int row = blockIdx.x;
    int t = threadIdx.x;
    const float* x = hidden + (size_t)row * D_;

    float ss = 0.f, dm = 0.f;
    for (int i = t; i < D_; i += 256) {
        float v = x[i];
        ss += v * v;
        dm += v * w_mod[i];
    }
    ss = blockReduceSum(ss);
    dm = blockReduceSum(dm);

    float rs = rsqrtf(ss * (1.0f / D_) + 1e-6f);
    float logit = dm + b_mod[0];

    float dt = 0.f;
    for (int i = t; i < D_; i += 256) {
        float nv = x[i] * rs * g1[i];
        normed[(size_t)row * D_ + i] = nv;
        dt += nv * w_tok[i];
    }
    dt = blockReduceSum(dt);

    if (t == 0) {
        scores[row] = sigmoidf_(dt + b_tok[0]);
        active[row] = (logit > 0.0f) ? 1.0f : 0.0f;
        if (probs_out) probs_out[row] = sigmoidf_(logit);
    }
}

// ---------------------------------------------------------------------------
// K2: per-batch exact top-k threshold via bitonic sort (ascending), 1024 thr
// ---------------------------------------------------------------------------
__global__ void topk_kernel(const float* __restrict__ scores,
                            float* __restrict__ kth) {
    __shared__ float s[S_];
    int b = blockIdx.x;
    int t = threadIdx.x;
    s[t]        = scores[b * S_ + t];
    s[t + 1024] = scores[b * S_ + t + 1024];

    for (int size = 2; size <= S_; size <<= 1) {
        for (int stride = size >> 1; stride > 0; stride >>= 1) {
            __syncthreads();
            #pragma unroll
            for (int r = 0; r < 2; r++) {
                int i = t + r * 1024;
                int j = i ^ stride;
                if (j > i) {
                    float a = s[i], c = s[j];
                    bool asc = ((i & size) == 0);
                    if ((a > c) == asc) { s[i] = c; s[j] = a; }
                }
            }
        }
    }
    __syncthreads();
    if (t == 0) kth[b] = s[KTH_IDX];
}

// ---------------------------------------------------------------------------
// K3: token mask + row mask
// ---------------------------------------------------------------------------
__global__ void mask_kernel(const float* __restrict__ scores,
                            const float* __restrict__ kth,
                            const float* __restrict__ active,
                            float* __restrict__ rowmask,
                            float* __restrict__ out_mask) {
    int i = blockIdx.x * 256 + threadIdx.x;
    if (i < ROWS_) {
        int b = i >> 11;
        float tm = (scores[i] >= kth[b]) ? 1.0f : 0.0f;
        if (out_mask) out_mask[i] = tm;
        rowmask[i] = tm * active[i];
    }
}

// ---------------------------------------------------------------------------
// K4: rmsnorm(g2)
// ---------------------------------------------------------------------------
__global__ void rmsnorm_kernel(const float* __restrict__ x,
                               const float* __restrict__ g,
                               float* __restrict__ y) {
    int row = blockIdx.x;
    int t = threadIdx.x;
    const float* xr = x + (size_t)row * D_;
    float ss = 0.f;
    for (int i = t; i < D_; i += 256) { float v = xr[i]; ss += v * v; }
    ss = blockReduceSum(ss);
    float rs = rsqrtf(ss * (1.0f / D_) + 1e-6f);
    for (int i = t; i < D_; i += 256) y[(size_t)row * D_ + i] = xr[i] * rs * g[i];
}

// ---------------------------------------------------------------------------
// K5: tiled SGEMM, C[M,N] = A[M,K] @ B[K,N], with fused epilogues
//   EPI 0: C = acc
//   EPI 1: C = base + acc * rowscale[m]
//   EPI 2: C = elem * sigmoid(acc + bias[n])
//   EPI 3: C = silu(elem) * acc
// BM=BN=64, BK=16, 256 threads, 4x4 per thread
// ---------------------------------------------------------------------------
template <int EPI>
__global__ void __launch_bounds__(256)
sgemm64(const float* __restrict__ A, const float* __restrict__ Bm,
        float* __restrict__ C, int M, int N, int K,
        const float* __restrict__ base, const float* __restrict__ rowscale,
        const float* __restrict__ elem, const float* __restrict__ bias) {
    __shared__ float As[16][64];
    __shared__ float Bs[16][64];

    int bm = blockIdx.x * 64;
    int bn = blockIdx.y * 64;
    int tid = threadIdx.x;
    int tx = tid & 15;
    int ty = tid >> 4;

    int ar = tid >> 2;
    int ac = (tid & 3) << 2;
    int br = tid >> 4;
    int bc = (tid & 15) << 2;

    const float* Aptr = A + (size_t)(bm + ar) * K + ac;
    const float* Bptr = Bm + (size_t)br * N + bn + bc;

    float acc[4][4] = {};

    for (int k0 = 0; k0 < K; k0 += 16) {
        float4 av = *(const float4*)Aptr; Aptr += 16;
        float4 bv = *(const float4*)Bptr; Bptr += (size_t)16 * N;

        __syncthreads();
        As[ac + 0][ar] = av.x;
        As[ac + 1][ar] = av.y;
        As[ac + 2][ar] = av.z;
        As[ac + 3][ar] = av.w;
        *(float4*)&Bs[br][bc] = bv;
        __syncthreads();

        #pragma unroll
        for (int kk = 0; kk < 16; kk++) {
            float4 a = *(const float4*)&As[kk][ty * 4];
            float4 b = *(const float4*)&Bs[kk][tx * 4];
            acc[0][0] += a.x * b.x; acc[0][1] += a.x * b.y; acc[0][2] += a.x * b.z; acc[0][3] += a.x * b.w;
            acc[1][0] += a.y * b.x; acc[1][1] += a.y * b.y; acc[1][2] += a.y * b.z; acc[1][3] += a.y * b.w;
            acc[2][0] += a.z * b.x; acc[2][1] += a.z * b.y; acc[2][2] += a.z * b.z; acc[2][3] += a.z * b.w;
            acc[3][0] += a.w * b.x; acc[3][1] += a.w * b.y; acc[3][2] += a.w * b.z; acc[3][3] += a.w * b.w;
        }
    }

    #pragma unroll
    for (int i = 0; i < 4; i++) {
        int m = bm + ty * 4 + i;
        int n = bn + tx * 4;
        size_t idx = (size_t)m * N + n;
        float4 c;
        if (EPI == 0) {
            c.x = acc[i][0]; c.y = acc[i][1]; c.z = acc[i][2]; c.w = acc[i][3];
        } else if (EPI == 1) {
            float rsc = rowscale[m];
            float4 bb = *(const float4*)&base[idx];
            c.x = bb.x + acc[i][0] * rsc;
            c.y = bb.y + acc[i][1] * rsc;
            c.z = bb.z + acc[i][2] * rsc;
            c.w = bb.w + acc[i][3] * rsc;
        } else if (EPI == 2) {
            float4 e = *(const float4*)&elem[idx];
            float4 bi = *(const float4*)&bias[n];
            c.x = e.x * sigmoidf_(acc[i][0] + bi.x);
            c.y = e.y * sigmoidf_(acc[i][1] + bi.y);
            c.z = e.z * sigmoidf_(acc[i][2] + bi.z);
            c.w = e.w * sigmoidf_(acc[i][3] + bi.w);
        } else {
            float4 e = *(const float4*)&elem[idx];
            c.x = (e.x * sigmoidf_(e.x)) * acc[i][0];
            c.y = (e.y * sigmoidf_(e.y)) * acc[i][1];
            c.z = (e.z * sigmoidf_(e.z)) * acc[i][2];
            c.w = (e.w * sigmoidf_(e.w)) * acc[i][3];
        }
        *(float4*)&C[idx] = c;
    }
}

// ---------------------------------------------------------------------------
// K6: causal flash attention. grid=(32 qtiles, 12 heads, 2 batch), 64 thr.
// Each thread owns one query row (full 64-dim q and o in registers).
// ---------------------------------------------------------------------------
__global__ void __launch_bounds__(64)
attn_kernel(const float* __restrict__ Q, const float* __restrict__ Kt,
            const float* __restrict__ V, float* __restrict__ O) {
    __shared__ float Ks[64][64];
    __shared__ float Vs[64][64];

    int qt = blockIdx.x;
    int h  = blockIdx.y;
    int b  = blockIdx.z;
    int tid = threadIdx.x;

    size_t rowbase = (size_t)b * S_;
    int hoff = h * DH_;
    int qrow = qt * 64 + tid;

    float q[64];
    {
        const float* qp = Q + (rowbase + qrow) * D_ + hoff;
        #pragma unroll
        for (int d = 0; d < 64; d++) q[d] = qp[d] * 0.125f;   // 1/sqrt(64)
    }
    float o[64];
    #pragma unroll
    for (int d = 0; d < 64; d++) o[d] = 0.f;
    float m = -1e30f, l = 0.f;

    for (int kt = 0; kt <= qt; kt++) {
        __syncthreads();
        #pragma unroll 8
        for (int i = 0; i < 64; i++) {
            size_t gidx = (rowbase + kt * 64 + i) * D_ + hoff + tid;
            Ks[i][tid] = Kt[gidx];
            Vs[i][tid] = V[gidx];
        }
        __syncthreads();

        int jmax = (kt == qt) ? (tid + 1) : 64;
        const float4* K4 = (const float4*)&Ks[0][0];
        const float4* V4 = (const float4*)&Vs[0][0];
        for (int j = 0; j < jmax; j++) {
            float s = 0.f;
            #pragma unroll
            for (int d4 = 0; d4 < 16; d4++) {
                float4 kv = K4[j * 16 + d4];
                s += q[d4 * 4 + 0] * kv.x + q[d4 * 4 + 1] * kv.y
                   + q[d4 * 4 + 2] * kv.z + q[d4 * 4 + 3] * kv.w;
            }
            if (s <= m) {
                float p = __expf(s - m);
                l += p;
                #pragma unroll
                for (int d4 = 0; d4 < 16; d4++) {
                    float4 vv = V4[j * 16 + d4];
                    o[d4 * 4 + 0] += p * vv.x;
                    o[d4 * 4 + 1] += p * vv.y;
                    o[d4 * 4 + 2] += p * vv.z;
                    o[d4 * 4 + 3] += p * vv.w;
                }
            } else {
                float scale = __expf(m - s);
                m = s;
                l = l * scale + 1.0f;
                #pragma unroll
                for (int d4 = 0; d4 < 16; d4++) {
                    float4 vv = V4[j * 16 + d4];
                    o[d4 * 4 + 0] = o[d4 * 4 + 0] * scale + vv.x;
                    o[d4 * 4 + 1] = o[d4 * 4 + 1] * scale + vv.y;
                    o[d4 * 4 + 2] = o[d4 * 4 + 2] * scale + vv.z;
                    o[d4 * 4 + 3] = o[d4 * 4 + 3] * scale + vv.w;
                }
            }
        }
    }

    float inv = 1.0f / l;
    float* op = O + (rowbase + qrow) * D_ + hoff;
    #pragma unroll
    for (int d4 = 0; d4 < 16; d4++) {
        float4 c;
        c.x = o[d4 * 4 + 0] * inv;
        c.y = o[d4 * 4 + 1] * inv;
        c.z = o[d4 * 4 + 2] * inv;
        c.w = o[d4 * 4 + 3] * inv;
        *(float4*)&op[d4 * 4] = c;
    }
}

// ---------------------------------------------------------------------------
// Launch
// ---------------------------------------------------------------------------
extern "C" void kernel_launch(void* const* d_in, const int* in_sizes, int n_in,
                              void* d_out, int out_size) {
    const float* hidden = (const float*)d_in[0];
    // d_in[1] = attn_mask (tril, applied analytically), d_in[2] = temperature(=1)
    const float* wq     = (const float*)d_in[3];
    const float* wk     = (const float*)d_in[4];
    const float* wv     = (const float*)d_in[5];
    const float* wo     = (const float*)d_in[6];
    const float* w1     = (const float*)d_in[7];
    const float* w3     = (const float*)d_in[8];
    const float* w2     = (const float*)d_in[9];
    const float* g1     = (const float*)d_in[10];
    const float* g2     = (const float*)d_in[11];
    const float* w_mod  = (const float*)d_in[12];
    const float* b_mod  = (const float*)d_in[13];
    const float* w_tok  = (const float*)d_in[14];
    const float* b_tok  = (const float*)d_in[15];
    const float* w_gate = (const float*)d_in[16];
    const float* b_gate = (const float*)d_in[17];

    float* out = (float*)d_out;
    float* out_hidden = out;
    bool full = (out_size >= ROWS_ * D_ + 2 * ROWS_);
    float* out_probs = full ? out + (size_t)ROWS_ * D_ : nullptr;
    float* out_mask  = full ? out + (size_t)ROWS_ * D_ + ROWS_ : nullptr;

    float *normed, *q, *k, *v, *ctx, *h2, *n2, *gated, *h1, *u;
    float *scores, *active, *rowmask, *kth;
    cudaGetSymbolAddress((void**)&normed,  g_normed);
    cudaGetSymbolAddress((void**)&q,       g_q);
    cudaGetSymbolAddress((void**)&k,       g_k);
    cudaGetSymbolAddress((void**)&v,       g_v);
    cudaGetSymbolAddress((void**)&ctx,     g_ctx);
    cudaGetSymbolAddress((void**)&h2,      g_h2);
    cudaGetSymbolAddress((void**)&n2,      g_n2);
    cudaGetSymbolAddress((void**)&gated,   g_gated);
    cudaGetSymbolAddress((void**)&h1,      g_h1);
    cudaGetSymbolAddress((void**)&u,       g_u);
    cudaGetSymbolAddress((void**)&scores,  g_scores);
    cudaGetSymbolAddress((void**)&active,  g_active);
    cudaGetSymbolAddress((void**)&rowmask, g_rowmask);
    cudaGetSymbolAddress((void**)&kth,     g_kth);

    // 1. router + rmsnorm(g1) + token scores
    pre_kernel<<<ROWS_, 256>>>(hidden, g1, w_mod, b_mod, w_tok, b_tok,
                               normed, scores, active, out_probs);
    // 2. exact top-k threshold per batch
    topk_kernel<<<B_, 1024>>>(scores, kth);
    // 3. masks
    mask_kernel<<<ROWS_ / 256, 256>>>(scores, kth, active, rowmask, out_mask);

    // 4. QKV projections
    dim3 gD(ROWS_ / 64, D_ / 64);
    sgemm64<0><<<gD, 256>>>(normed, wq, q, ROWS_, D_, D_, nullptr, nullptr, nullptr, nullptr);
    sgemm64<0><<<gD, 256>>>(normed, wk, k, ROWS_, D_, D_, nullptr, nullptr, nullptr, nullptr);
    sgemm64<0><<<gD, 256>>>(normed, wv, v, ROWS_, D_, D_, nullptr, nullptr, nullptr, nullptr);

    // 5. causal attention
    attn_kernel<<<dim3(S_ / 64, H_, B_), 64>>>(q, k, v, ctx);

    // 6. output projection + token/depth masked residual add
    sgemm64<1><<<gD, 256>>>(ctx, wo, h2, ROWS_, D_, D_, hidden, rowmask, nullptr, nullptr);

    // 7. rmsnorm(g2)
    rmsnorm_kernel<<<ROWS_, 256>>>(h2, g2, n2);

    // 8. ACM gate: n2 * sigmoid(n2 @ w_gate + b_gate)
    sgemm64<2><<<gD, 256>>>(n2, w_gate, gated, ROWS_, D_, D_, nullptr, nullptr, n2, b_gate);

    // 9. SwiGLU up projections
    dim3 gF(ROWS_ / 64, F_ / 64);
    sgemm64<0><<<gF, 256>>>(gated, w1, h1, ROWS_, F_, D_, nullptr, nullptr, nullptr, nullptr);
    sgemm64<3><<<gF, 256>>>(gated, w3, u, ROWS_, F_, D_, nullptr, nullptr, h1, nullptr);

    // 10. down projection + active-masked residual add -> final hidden (to d_out)
    sgemm64<1><<<gD, 256>>>(u, w2, out_hidden, ROWS_, D_, F_, h2, active, nullptr, nullptr);
}

// round 7
// speedup vs baseline: 1.5251x; 1.5251x over previous
#include <cuda_runtime.h>
#include <cuda_bf16.h>
#include <math.h>
#include <stdint.h>

// ---------------------------------------------------------------------------
// Problem constants
// ---------------------------------------------------------------------------
#define B_    2
#define S_    2048
#define D_    768
#define H_    12
#define DH_   64
#define F_    2048
#define ROWS_ (B_ * S_)          // 4096
#define KKEEP 1228               // int(2048*0.6)
#define KTH_IDX (S_ - KKEEP)     // 820
#define QKV_N (3 * D_)           // 2304
#define QKV_STRIDE QKV_N

// ---------------------------------------------------------------------------
// Scratch (static device allocations)
// ---------------------------------------------------------------------------
__device__ float g_normed[ROWS_ * D_];
__device__ float g_qkv[ROWS_ * QKV_N];
__device__ float g_ctx[ROWS_ * D_];
__device__ float g_h2[ROWS_ * D_];
__device__ float g_n2[ROWS_ * D_];
__device__ float g_gated[ROWS_ * D_];
__device__ float g_h1[ROWS_ * F_];
__device__ float g_u[ROWS_ * F_];
__device__ float g_scores[ROWS_];
__device__ float g_active[ROWS_];
__device__ float g_rowmask[ROWS_];
__device__ float g_kth[B_];
// transposed weights ([N][K] K-major so GEMM is C = A @ Wt^T)
__device__ float g_wqkvT[QKV_N * D_];
__device__ float g_woT[D_ * D_];
__device__ float g_wgT[D_ * D_];
__device__ float g_w1T[F_ * D_];
__device__ float g_w3T[F_ * D_];
__device__ float g_w2T[D_ * F_];

// ---------------------------------------------------------------------------
// Helpers
// ---------------------------------------------------------------------------
__device__ __forceinline__ float sigmoidf_(float x) {
    return 1.0f / (1.0f + __expf(-x));
}
__device__ __forceinline__ uint32_t cvt_tf32(float x) {
    uint32_t r; asm("cvt.rna.tf32.f32 %0, %1;" : "=r"(r) : "f"(x)); return r;
}

// m16n8k8 tf32 MMA (sm_80+ base-target instruction; compiles for sm_103)
#define MMA_TF32(d, a, b) \
    asm volatile("mma.sync.aligned.m16n8k8.row.col.f32.tf32.tf32.f32 " \
        "{%0,%1,%2,%3}, {%4,%5,%6,%7}, {%8,%9}, {%0,%1,%2,%3};" \
        : "+f"((d)[0]), "+f"((d)[1]), "+f"((d)[2]), "+f"((d)[3]) \
        : "r"((a)[0]), "r"((a)[1]), "r"((a)[2]), "r"((a)[3]), \
          "r"((b)[0]), "r"((b)[1]))

// ---------------------------------------------------------------------------
// tf32 tensor-core GEMM: C[M,N] = A[M,K] @ Bt[N,K]^T, fused epilogues.
// 256 thr, 128x128 tile, BK=32, double-buffered SMEM, stride-36 rows
// (bank = (4m + k) mod 32 -> conflict-free fragment reads and stores).
//   EPI 0: C = acc
//   EPI 1: C = base + acc * rowscale[m]
//   EPI 2: C = elem * sigmoid(acc + bias[n])
//   EPI 3: C = silu(elem) * acc
// ---------------------------------------------------------------------------
#define TG_LDA   36               // words per row (32 + 4 pad)
#define TG_BUF   4608             // floats per (128 x 36) tile
#define TG_SMEM_SZ (4 * TG_BUF * 4)   // A0,B0,A1,B1 = 73728 bytes

__device__ __forceinline__ void tg_gload(const float* __restrict__ A,
                                         const float* __restrict__ Bt,
                                         int bm, int bn, int K, int kb, int tid,
                                         float4* pa, float4* pb) {
    #pragma unroll
    for (int i = 0; i < 4; i++) {
        int f = i * 256 + tid;
        int r = f >> 3, c4 = f & 7;
        pa[i] = *(const float4*)(A  + (size_t)(bm + r) * K + kb * 32 + c4 * 4);
        pb[i] = *(const float4*)(Bt + (size_t)(bn + r) * K + kb * 32 + c4 * 4);
    }
}

__device__ __forceinline__ void tg_sstore(float* As, float* Bs, int tid,
                                          const float4* pa, const float4* pb) {
    #pragma unroll
    for (int i = 0; i < 4; i++) {
        int f = i * 256 + tid;
        int r = f >> 3, c4 = f & 7;
        uint4 wa, wb;
        wa.x = cvt_tf32(pa[i].x); wa.y = cvt_tf32(pa[i].y);
        wa.z = cvt_tf32(pa[i].z); wa.w = cvt_tf32(pa[i].w);
        wb.x = cvt_tf32(pb[i].x); wb.y = cvt_tf32(pb[i].y);
        wb.z = cvt_tf32(pb[i].z); wb.w = cvt_tf32(pb[i].w);
        *(uint4*)(As + r * TG_LDA + c4 * 4) = wa;
        *(uint4*)(Bs + r * TG_LDA + c4 * 4) = wb;
    }
}

template <int EPI>
__device__ __forceinline__ void tg_store2(float* __restrict__ C,
                                          const float* __restrict__ base_in,
                                          const float* __restrict__ rowscale,
                                          const float* __restrict__ elem,
                                          const float* __restrict__ bias,
                                          int m, int n, int N, float a0, float a1) {
    size_t idx = (size_t)m * N + n;
    float2 c;
    if (EPI == 0) {
        c.x = a0; c.y = a1;
    } else if (EPI == 1) {
        float rsc = rowscale[m];
        float2 bb = *(const float2*)&base_in[idx];
        c.x = bb.x + a0 * rsc; c.y = bb.y + a1 * rsc;
    } else if (EPI == 2) {
        float2 e = *(const float2*)&elem[idx];
        float2 bi = *(const float2*)&bias[n];
        c.x = e.x * sigmoidf_(a0 + bi.x);
        c.y = e.y * sigmoidf_(a1 + bi.y);
    } else {
        float2 e = *(const float2*)&elem[idx];
        c.x = (e.x * sigmoidf_(e.x)) * a0;
        c.y = (e.y * sigmoidf_(e.y)) * a1;
    }
    *(float2*)&C[idx] = c;
}

template <int EPI>
__global__ void __launch_bounds__(256)
tgemm(const float* __restrict__ A, const float* __restrict__ Bt, float* __restrict__ C,
      int M, int N, int K,
      const float* __restrict__ base_in, const float* __restrict__ rowscale,
      const float* __restrict__ elem, const float* __restrict__ bias) {
    extern __shared__ float sm[];
    float* bufA[2] = { sm,               sm + 2 * TG_BUF };
    float* bufB[2] = { sm + TG_BUF,      sm + 3 * TG_BUF };

    int tid  = threadIdx.x;
    int lane = tid & 31, warp = tid >> 5;
    int g = lane >> 2, t = lane & 3;
    int wm = warp & 1, wn = warp >> 1;     // 2 x 4 warp grid, warp tile 64x32
    int bm = blockIdx.x * 128, bn = blockIdx.y * 128;
    const int NKB = K >> 5;

    float acc[4][4][4];
    #pragma unroll
    for (int i = 0; i < 4; i++)
        #pragma unroll
        for (int j = 0; j < 4; j++)
            #pragma unroll
            for (int l = 0; l < 4; l++) acc[i][j][l] = 0.f;

    float4 pa[4], pb[4];
    tg_gload(A, Bt, bm, bn, K, 0, tid, pa, pb);
    tg_sstore(bufA[0], bufB[0], tid, pa, pb);
    __syncthreads();

    for (int kb = 0; kb < NKB; kb++) {
        int buf = kb & 1;
        if (kb + 1 < NKB) tg_gload(A, Bt, bm, bn, K, kb + 1, tid, pa, pb);

        const uint32_t* As = (const uint32_t*)bufA[buf];
        const uint32_t* Bs = (const uint32_t*)bufB[buf];
        #pragma unroll
        for (int kk = 0; kk < 4; kk++) {
            int k0 = kk * 8;
            uint32_t af[4][4], bf[4][2];
            #pragma unroll
            for (int mt = 0; mt < 4; mt++) {
                int m = wm * 64 + mt * 16 + g;
                af[mt][0] = As[m * TG_LDA + k0 + t];
                af[mt][1] = As[(m + 8) * TG_LDA + k0 + t];
                af[mt][2] = As[m * TG_LDA + k0 + t + 4];
                af[mt][3] = As[(m + 8) * TG_LDA + k0 + t + 4];
            }
            #pragma unroll
            for (int nt = 0; nt < 4; nt++) {
                int n = wn * 32 + nt * 8 + g;
                bf[nt][0] = Bs[n * TG_LDA + k0 + t];
                bf[nt][1] = Bs[n * TG_LDA + k0 + t + 4];
            }
            #pragma unroll
            for (int mt = 0; mt < 4; mt++)
                #pragma unroll
                for (int nt = 0; nt < 4; nt++)
                    MMA_TF32(acc[mt][nt], af[mt], bf[nt]);
        }

        if (kb + 1 < NKB) {
            __syncthreads();
            tg_sstore(bufA[buf ^ 1], bufB[buf ^ 1], tid, pa, pb);
            __syncthreads();
        }
    }

    // epilogue: c0/c1 = (row g, cols 2t,2t+1); c2/c3 = row g+8
    #pragma unroll
    for (int mt = 0; mt < 4; mt++) {
        #pragma unroll
        for (int nt = 0; nt < 4; nt++) {
            int m = bm + wm * 64 + mt * 16 + g;
            int n = bn + wn * 32 + nt * 8 + 2 * t;
            tg_store2<EPI>(C, base_in, rowscale, elem, bias, m,     n, N,
                           acc[mt][nt][0], acc[mt][nt][1]);
            tg_store2<EPI>(C, base_in, rowscale, elem, bias, m + 8, n, N,
                           acc[mt][nt][2], acc[mt][nt][3]);
        }
    }
}

// ---------------------------------------------------------------------------
// transpose: in [R x C] -> out [C x R]
// ---------------------------------------------------------------------------
__global__ void transpose_kernel(const float* __restrict__ in, float* __restrict__ out,
                                 int R, int C) {
    __shared__ float tile[32][33];
    int c0 = blockIdx.x * 32, r0 = blockIdx.y * 32;
    int x = c0 + threadIdx.x, y = r0 + threadIdx.y;
    #pragma unroll
    for (int j = 0; j < 32; j += 8)
        tile[threadIdx.y + j][threadIdx.x] = in[(size_t)(y + j) * C + x];
    __syncthreads();
    x = r0 + threadIdx.x; y = c0 + threadIdx.y;
    #pragma unroll
    for (int j = 0; j < 32; j += 8)
        out[(size_t)(y + j) * R + x] = tile[threadIdx.x][threadIdx.y + j];
}

// ---------------------------------------------------------------------------
// block reduce
// ---------------------------------------------------------------------------
__device__ float blockReduceSum(float v) {
    __shared__ float sh[32];
    int lane = threadIdx.x & 31;
    int wid  = threadIdx.x >> 5;
    #pragma unroll
    for (int o = 16; o; o >>= 1) v += __shfl_down_sync(0xFFFFFFFFu, v, o);
    if (lane == 0) sh[wid] = v;
    __syncthreads();
    int nw = blockDim.x >> 5;
    v = (threadIdx.x < nw) ? sh[threadIdx.x] : 0.0f;
    if (wid == 0) {
        #pragma unroll
        for (int o = 16; o; o >>= 1) v += __shfl_down_sync(0xFFFFFFFFu, v, o);
        if (lane == 0) sh[0] = v;
    }
    __syncthreads();
    float r = sh[0];
    __syncthreads();
    return r;
}

// ---------------------------------------------------------------------------
// K1: fused depth router + rmsnorm(g1) + token score (exact fp32)
// ---------------------------------------------------------------------------
__global__ void pre_kernel(const float* __restrict__ hidden,
                           const float* __restrict__ g1,
                           const float* __restrict__ w_mod,
                           const float* __restrict__ b_mod,
                           const float* __restrict__ w_tok,
                           const float* __restrict__ b_tok,
                           float* __restrict__ normed,
                           float* __restrict__ scores,
                           float* __restrict__ active,
                           float* __restrict__ probs_out) {
    int row = blockIdx.x;
    int t = threadIdx.x;
    const float* x = hidden + (size_t)row * D_;

    float ss = 0.f, dm = 0.f;
    for (int i = t; i < D_; i += 256) {
        float v = x[i];
        ss += v * v;
        dm += v * w_mod[i];
    }
    ss = blockReduceSum(ss);
    dm = blockReduceSum(dm);

    float rs = rsqrtf(ss * (1.0f / D_) + 1e-6f);
    float logit = dm + b_mod[0];

    float dt = 0.f;
    for (int i = t; i < D_; i += 256) {
        float nv = x[i] * rs * g1[i];
        normed[(size_t)row * D_ + i] = nv;
        dt += nv * w_tok[i];
    }
    dt = blockReduceSum(dt);

    if (t == 0) {
        scores[row] = sigmoidf_(dt + b_tok[0]);
        active[row] = (logit > 0.0f) ? 1.0f : 0.0f;
        if (probs_out) probs_out[row] = sigmoidf_(logit);
    }
}

// ---------------------------------------------------------------------------
// K2: per-batch exact top-k threshold via bitonic sort
// ---------------------------------------------------------------------------
__global__ void topk_kernel(const float* __restrict__ scores,
                            float* __restrict__ kth) {
    __shared__ float s[S_];
    int b = blockIdx.x;
    int t = threadIdx.x;
    s[t]        = scores[b * S_ + t];
    s[t + 1024] = scores[b * S_ + t + 1024];

    for (int size = 2; size <= S_; size <<= 1) {
        for (int stride = size >> 1; stride > 0; stride >>= 1) {
            __syncthreads();
            #pragma unroll
            for (int r = 0; r < 2; r++) {
                int i = t + r * 1024;
                int j = i ^ stride;
                if (j > i) {
                    float a = s[i], c = s[j];
                    bool asc = ((i & size) == 0);
                    if ((a > c) == asc) { s[i] = c; s[j] = a; }
                }
            }
        }
    }
    __syncthreads();
    if (t == 0) kth[b] = s[KTH_IDX];
}

// ---------------------------------------------------------------------------
// K3: masks
// ---------------------------------------------------------------------------
__global__ void mask_kernel(const float* __restrict__ scores,
                            const float* __restrict__ kth,
                            const float* __restrict__ active,
                            float* __restrict__ rowmask,
                            float* __restrict__ out_mask) {
    int i = blockIdx.x * 256 + threadIdx.x;
    if (i < ROWS_) {
        int b = i >> 11;
        float tm = (scores[i] >= kth[b]) ? 1.0f : 0.0f;
        if (out_mask) out_mask[i] = tm;
        rowmask[i] = tm * active[i];
    }
}

// ---------------------------------------------------------------------------
// K4: rmsnorm(g2)
// ---------------------------------------------------------------------------
__global__ void rmsnorm_kernel(const float* __restrict__ x,
                               const float* __restrict__ g,
                               float* __restrict__ y) {
    int row = blockIdx.x;
    int t = threadIdx.x;
    const float* xr = x + (size_t)row * D_;
    float ss = 0.f;
    for (int i = t; i < D_; i += 256) { float v = xr[i]; ss += v * v; }
    ss = blockReduceSum(ss);
    float rs = rsqrtf(ss * (1.0f / D_) + 1e-6f);
    for (int i = t; i < D_; i += 256) y[(size_t)row * D_ + i] = xr[i] * rs * g[i];
}

// ---------------------------------------------------------------------------
// K6: causal flash attention over fused QKV buffer (stride 2304)
// ---------------------------------------------------------------------------
__global__ void __launch_bounds__(64)
attn_kernel(const float* __restrict__ QKV, float* __restrict__ O) {
    __shared__ float Ks[64][64];
    __shared__ float Vs[64][64];

    int qt = blockIdx.x;
    int h  = blockIdx.y;
    int b  = blockIdx.z;
    int tid = threadIdx.x;

    size_t rowbase = (size_t)b * S_;
    int hoff = h * DH_;
    int qrow = qt * 64 + tid;

    float q[64];
    {
        const float* qp = QKV + (rowbase + qrow) * QKV_STRIDE + hoff;
        #pragma unroll
        for (int d = 0; d < 64; d++) q[d] = qp[d] * 0.125f;  // 1/sqrt(64)
    }
    float o[64];
    #pragma unroll
    for (int d = 0; d < 64; d++) o[d] = 0.f;
    float m = -1e30f, l = 0.f;

    for (int kt = 0; kt <= qt; kt++) {
        __syncthreads();
        #pragma unroll 8
        for (int i = 0; i < 64; i++) {
            size_t gidx = (rowbase + kt * 64 + i) * QKV_STRIDE + hoff + tid;
            Ks[i][tid] = QKV[gidx + D_];
            Vs[i][tid] = QKV[gidx + 2 * D_];
        }
        __syncthreads();

        int jmax = (kt == qt) ? (tid + 1) : 64;
        const float4* K4 = (const float4*)&Ks[0][0];
        const float4* V4 = (const float4*)&Vs[0][0];
        for (int j = 0; j < jmax; j++) {
            float s = 0.f;
            #pragma unroll
            for (int d4 = 0; d4 < 16; d4++) {
                float4 kv = K4[j * 16 + d4];
                s += q[d4 * 4 + 0] * kv.x + q[d4 * 4 + 1] * kv.y
                   + q[d4 * 4 + 2] * kv.z + q[d4 * 4 + 3] * kv.w;
            }
            if (s <= m) {
                float p = __expf(s - m);
                l += p;
                #pragma unroll
                for (int d4 = 0; d4 < 16; d4++) {
                    float4 vv = V4[j * 16 + d4];
                    o[d4 * 4 + 0] += p * vv.x;
                    o[d4 * 4 + 1] += p * vv.y;
                    o[d4 * 4 + 2] += p * vv.z;
                    o[d4 * 4 + 3] += p * vv.w;
                }
            } else {
                float scale = __expf(m - s);
                m = s;
                l = l * scale + 1.0f;
                #pragma unroll
                for (int d4 = 0; d4 < 16; d4++) {
                    float4 vv = V4[j * 16 + d4];
                    o[d4 * 4 + 0] = o[d4 * 4 + 0] * scale + vv.x;
                    o[d4 * 4 + 1] = o[d4 * 4 + 1] * scale + vv.y;
                    o[d4 * 4 + 2] = o[d4 * 4 + 2] * scale + vv.z;
                    o[d4 * 4 + 3] = o[d4 * 4 + 3] * scale + vv.w;
                }
            }
        }
    }

    float inv = 1.0f / l;
    float* op = O + (rowbase + qrow) * D_ + hoff;
    #pragma unroll
    for (int d4 = 0; d4 < 16; d4++) {
        float4 c;
        c.x = o[d4 * 4 + 0] * inv;
        c.y = o[d4 * 4 + 1] * inv;
        c.z = o[d4 * 4 + 2] * inv;
        c.w = o[d4 * 4 + 3] * inv;
        *(float4*)&op[d4 * 4] = c;
    }
}

// ---------------------------------------------------------------------------
// Launch
// ---------------------------------------------------------------------------
extern "C" void kernel_launch(void* const* d_in, const int* in_sizes, int n_in,
                              void* d_out, int out_size) {
    const float* hidden = (const float*)d_in[0];
    const float* wq     = (const float*)d_in[3];
    const float* wk     = (const float*)d_in[4];
    const float* wv     = (const float*)d_in[5];
    const float* wo     = (const float*)d_in[6];
    const float* w1     = (const float*)d_in[7];
    const float* w3     = (const float*)d_in[8];
    const float* w2     = (const float*)d_in[9];
    const float* g1     = (const float*)d_in[10];
    const float* g2     = (const float*)d_in[11];
    const float* w_mod  = (const float*)d_in[12];
    const float* b_mod  = (const float*)d_in[13];
    const float* w_tok  = (const float*)d_in[14];
    const float* b_tok  = (const float*)d_in[15];
    const float* w_gate = (const float*)d_in[16];
    const float* b_gate = (const float*)d_in[17];

    float* out = (float*)d_out;
    float* out_hidden = out;
    bool full = (out_size >= ROWS_ * D_ + 2 * ROWS_);
    float* out_probs = full ? out + (size_t)ROWS_ * D_ : nullptr;
    float* out_mask  = full ? out + (size_t)ROWS_ * D_ + ROWS_ : nullptr;

    float *normed, *qkv, *ctx, *h2, *n2, *gated, *h1, *u;
    float *scores, *active, *rowmask, *kth;
    float *wqkvT, *woT, *wgT, *w1T, *w3T, *w2T;
    cudaGetSymbolAddress((void**)&normed,  g_normed);
    cudaGetSymbolAddress((void**)&qkv,     g_qkv);
    cudaGetSymbolAddress((void**)&ctx,     g_ctx);
    cudaGetSymbolAddress((void**)&h2,      g_h2);
    cudaGetSymbolAddress((void**)&n2,      g_n2);
    cudaGetSymbolAddress((void**)&gated,   g_gated);
    cudaGetSymbolAddress((void**)&h1,      g_h1);
    cudaGetSymbolAddress((void**)&u,       g_u);
    cudaGetSymbolAddress((void**)&scores,  g_scores);
    cudaGetSymbolAddress((void**)&active,  g_active);
    cudaGetSymbolAddress((void**)&rowmask, g_rowmask);
    cudaGetSymbolAddress((void**)&kth,     g_kth);
    cudaGetSymbolAddress((void**)&wqkvT,   g_wqkvT);
    cudaGetSymbolAddress((void**)&woT,     g_woT);
    cudaGetSymbolAddress((void**)&wgT,     g_wgT);
    cudaGetSymbolAddress((void**)&w1T,     g_w1T);
    cudaGetSymbolAddress((void**)&w3T,     g_w3T);
    cudaGetSymbolAddress((void**)&w2T,     g_w2T);

    cudaFuncSetAttribute(tgemm<0>, cudaFuncAttributeMaxDynamicSharedMemorySize, TG_SMEM_SZ);
    cudaFuncSetAttribute(tgemm<1>, cudaFuncAttributeMaxDynamicSharedMemorySize, TG_SMEM_SZ);
    cudaFuncSetAttribute(tgemm<2>, cudaFuncAttributeMaxDynamicSharedMemorySize, TG_SMEM_SZ);
    cudaFuncSetAttribute(tgemm<3>, cudaFuncAttributeMaxDynamicSharedMemorySize, TG_SMEM_SZ);

    // 0. transpose weights into [N][K] K-major buffers
    dim3 tb(32, 8);
    transpose_kernel<<<dim3(D_ / 32, D_ / 32), tb>>>(wq, wqkvT, D_, D_);
    transpose_kernel<<<dim3(D_ / 32, D_ / 32), tb>>>(wk, wqkvT + D_ * D_, D_, D_);
    transpose_kernel<<<dim3(D_ / 32, D_ / 32), tb>>>(wv, wqkvT + 2 * D_ * D_, D_, D_);
    transpose_kernel<<<dim3(D_ / 32, D_ / 32), tb>>>(wo, woT, D_, D_);
    transpose_kernel<<<dim3(D_ / 32, D_ / 32), tb>>>(w_gate, wgT, D_, D_);
    transpose_kernel<<<dim3(F_ / 32, D_ / 32), tb>>>(w1, w1T, D_, F_);
    transpose_kernel<<<dim3(F_ / 32, D_ / 32), tb>>>(w3, w3T, D_, F_);
    transpose_kernel<<<dim3(D_ / 32, F_ / 32), tb>>>(w2, w2T, F_, D_);

    // 1. router + rmsnorm(g1) + token scores (exact fp32)
    pre_kernel<<<ROWS_, 256>>>(hidden, g1, w_mod, b_mod, w_tok, b_tok,
                               normed, scores, active, out_probs);
    // 2. exact top-k threshold
    topk_kernel<<<B_, 1024>>>(scores, kth);
    // 3. masks
    mask_kernel<<<ROWS_ / 256, 256>>>(scores, kth, active, rowmask, out_mask);

    // 4. fused QKV projection (tf32 mma.sync tensor cores)
    tgemm<0><<<dim3(ROWS_ / 128, QKV_N / 128), 256, TG_SMEM_SZ>>>(
        normed, wqkvT, qkv, ROWS_, QKV_N, D_, nullptr, nullptr, nullptr, nullptr);

    // 5. causal attention
    attn_kernel<<<dim3(S_ / 64, H_, B_), 64>>>(qkv, ctx);

    // 6. output projection + masked residual
    tgemm<1><<<dim3(ROWS_ / 128, D_ / 128), 256, TG_SMEM_SZ>>>(
        ctx, woT, h2, ROWS_, D_, D_, hidden, rowmask, nullptr, nullptr);

    // 7. rmsnorm(g2)
    rmsnorm_kernel<<<ROWS_, 256>>>(h2, g2, n2);

    // 8. ACM gate
    tgemm<2><<<dim3(ROWS_ / 128, D_ / 128), 256, TG_SMEM_SZ>>>(
        n2, wgT, gated, ROWS_, D_, D_, nullptr, nullptr, n2, b_gate);

    // 9. SwiGLU up projections
    tgemm<0><<<dim3(ROWS_ / 128, F_ / 128), 256, TG_SMEM_SZ>>>(
        gated, w1T, h1, ROWS_, F_, D_, nullptr, nullptr, nullptr, nullptr);
    tgemm<3><<<dim3(ROWS_ / 128, F_ / 128), 256, TG_SMEM_SZ>>>(
        gated, w3T, u, ROWS_, F_, D_, nullptr, nullptr, h1, nullptr);

    // 10. down projection + active-masked residual -> final hidden
    tgemm<1><<<dim3(ROWS_ / 128, D_ / 128), 256, TG_SMEM_SZ>>>(
        u, w2T, out_hidden, ROWS_, D_, F_, h2, active, nullptr, nullptr);
}